// round 14
// baseline (speedup 1.0000x reference)
#include <cuda_runtime.h>
#include <cuda_fp16.h>
#include <cstdint>

#define NN 100000
#define NE 1000000
#define NGR 512

// ---------------- scratch ----------------
// NOTE: g_cnt/g_atts/g_degs/g_bsum/g_tick are zeroed at the TAIL of k_poolmlp
// (previous run) -- first run relies on static zero-init of device globals.
__device__ float g_atts[NN];      // src-side attention sum (atomic)
__device__ int   g_degs[NN];      // src-side degree (atomic)
__device__ float g_natt[NN];      // final node attention (written by last gather)
__device__ int   g_cnt[NN];       // in-degree (CSR row counts)
__device__ int   g_rs[NN];        // CSR row start
__device__ int   g_cur[NN];       // CSR fill cursor
__device__ int   g_bsum[128];     // chained-scan flags
__device__ int   g_tick;
__device__ float4 g_ce[NE];       // CSR: {src_as_bits, w, atten, pad}
__device__ __half g_Wh[9 * 4096]; // fp16 weights: [layer][mat(W1,W2,W3)][64k][64n]
__device__ __half g_hh[NN * 64];  // h in fp16
__device__ __half g_Ah[NN * 64];  // A = h@W1+b1
__device__ __half g_Bh[NN * 64];  // B = h@W2
__device__ __half g_Ch[NN * 64];  // C = h@W3+b3

__device__ __forceinline__ uint32_t smem_u32(const void* p) {
    uint32_t a;
    asm("{ .reg .u64 t; cvta.to.shared.u64 t, %1; cvt.u32.u64 %0, t; }" : "=r"(a) : "l"(p));
    return a;
}

// ------- init: node embedding + dst histogram + fp16 weight precompute -------
__global__ void k_initedge(const float* __restrict__ x, const float* __restrict__ w,
                           const float* __restrict__ b, const int* __restrict__ dst,
                           const float* __restrict__ l1w, const float* __restrict__ l2w,
                           const float* __restrict__ l3w) {
    int gid = blockIdx.x * 256 + threadIdx.x;
    if (gid < NE / 4) {
        int4 d = *(const int4*)&dst[gid * 4];
        atomicAdd(&g_cnt[d.x], 1); atomicAdd(&g_cnt[d.y], 1);
        atomicAdd(&g_cnt[d.z], 1); atomicAdd(&g_cnt[d.w], 1);
    }
    // fp16 weight conversion: 3 arrays x 12288 floats -> g_Wh[l][mat][4096]
    if (gid < 9216) {
        int i4 = gid * 4;
        int arr = i4 / 12288;            // 0=W1 stack,1=W2 stack,2=W3 stack
        int off = i4 % 12288;            // within [3 layers][4096]
        int l = off >> 12, loff = off & 4095;
        const float* srcp = (arr == 0) ? l1w : ((arr == 1) ? l2w : l3w);
        float4 v = *(const float4*)&srcp[off];
        __half2 lo = __floats2half2_rn(v.x, v.y);
        __half2 hi = __floats2half2_rn(v.z, v.w);
        uint2 pk = make_uint2(*(uint32_t*)&lo, *(uint32_t*)&hi);
        *(uint2*)&g_Wh[(l * 3 + arr) * 4096 + loff] = pk;
    }
    if (gid < NN * 32) {
        int i = gid >> 5, c = (gid & 31) * 2;
        float4 xv = *(const float4*)&x[i * 4];
        float h0 = b[c]     + xv.x * w[c]     + xv.y * w[64 + c]     + xv.z * w[128 + c]     + xv.w * w[192 + c];
        float h1 = b[c + 1] + xv.x * w[c + 1] + xv.y * w[64 + c + 1] + xv.z * w[128 + c + 1] + xv.w * w[192 + c + 1];
        *(__half2*)&g_hh[i * 64 + c] = __floats2half2_rn(h0, h1);
    }
}

// ---------------- single-pass chained exclusive scan: g_cnt -> g_rs, g_cur ----
__global__ void k_scan() {
    __shared__ int sm_t, sm_prev, wsum[8];
    int tid = threadIdx.x;
    if (tid == 0) sm_t = atomicAdd(&g_tick, 1);
    __syncthreads();
    int t = sm_t;
    int base = t * 1024 + tid * 4;
    int v0 = 0, v1 = 0, v2 = 0, v3 = 0;
    if (base + 3 < NN) {
        int4 q = *(const int4*)&g_cnt[base];
        v0 = q.x; v1 = q.y; v2 = q.z; v3 = q.w;
    } else {
        if (base < NN)     v0 = g_cnt[base];
        if (base + 1 < NN) v1 = g_cnt[base + 1];
        if (base + 2 < NN) v2 = g_cnt[base + 2];
        if (base + 3 < NN) v3 = g_cnt[base + 3];
    }
    int sloc = v0 + v1 + v2 + v3;
    int x = sloc;
#pragma unroll
    for (int o = 1; o < 32; o <<= 1) {
        int y = __shfl_up_sync(0xffffffffu, x, o);
        if ((tid & 31) >= o) x += y;
    }
    if ((tid & 31) == 31) wsum[tid >> 5] = x;
    __syncthreads();
    if (tid < 8) {
        int y = wsum[tid];
#pragma unroll
        for (int o = 1; o < 8; o <<= 1) {
            int z = __shfl_up_sync(0xffu, y, o);
            if (tid >= o) y += z;
        }
        wsum[tid] = y;
    }
    __syncthreads();
    int woff = (tid >= 32) ? wsum[(tid >> 5) - 1] : 0;
    int excl = x - sloc + woff;
    int total = wsum[7];
    if (tid == 0) {
        int prev = 0;
        if (t > 0) {
            int v;
            while ((v = atomicAdd(&g_bsum[t - 1], 0)) == 0) {}
            prev = v - 1;
        }
        atomicExch(&g_bsum[t], prev + total + 1);
        sm_prev = prev;
    }
    __syncthreads();
    int off = sm_prev + excl;
    if (base < NN)     { g_rs[base]     = off;                g_cur[base]     = off; }
    if (base + 1 < NN) { g_rs[base + 1] = off + v0;           g_cur[base + 1] = off + v0; }
    if (base + 2 < NN) { g_rs[base + 2] = off + v0 + v1;      g_cur[base + 2] = off + v0 + v1; }
    if (base + 3 < NN) { g_rs[base + 3] = off + v0 + v1 + v2; g_cur[base + 3] = off + v0 + v1 + v2; }
}

// ---------------- CSR fill + src-side atomics (4 edges/thread, 16B records) --
__global__ void k_fill(const int* __restrict__ src, const int* __restrict__ dst,
                       const float* __restrict__ attr, const float* __restrict__ atten) {
    int e4 = blockIdx.x * 256 + threadIdx.x;
    if (e4 * 4 >= NE) return;
    int4 s = *(const int4*)&src[e4 * 4];
    int4 d = *(const int4*)&dst[e4 * 4];
    float4 ar = *(const float4*)&attr[e4 * 4];
    float4 at = *(const float4*)&atten[e4 * 4];
    int p0 = atomicAdd(&g_cur[d.x], 1);
    int p1 = atomicAdd(&g_cur[d.y], 1);
    int p2 = atomicAdd(&g_cur[d.z], 1);
    int p3 = atomicAdd(&g_cur[d.w], 1);
    g_ce[p0] = make_float4(__int_as_float(s.x), ar.x * at.x, at.x, 0.f);
    g_ce[p1] = make_float4(__int_as_float(s.y), ar.y * at.y, at.y, 0.f);
    g_ce[p2] = make_float4(__int_as_float(s.z), ar.z * at.z, at.z, 0.f);
    g_ce[p3] = make_float4(__int_as_float(s.w), ar.w * at.w, at.w, 0.f);
    atomicAdd(&g_atts[s.x], at.x); atomicAdd(&g_atts[s.y], at.y);
    atomicAdd(&g_atts[s.z], at.z); atomicAdd(&g_atts[s.w], at.w);
    atomicAdd(&g_degs[s.x], 1);    atomicAdd(&g_degs[s.y], 1);
    atomicAdd(&g_degs[s.z], 1);    atomicAdd(&g_degs[s.w], 1);
}

// -------- layer GEMM via fp16 mma.m16n8k16: A=h@W1+b1, B=h@W2, C=h@W3+b3 -----
// 64 rows/block, 256 threads / 8 warps. W pre-converted fp16 in g_Wh.
// B fragments fetched 2 n8-tiles at a time via ldmatrix.x4.trans.
__global__ void __launch_bounds__(256, 3) k_gemm(int layer,
                                                 const float* __restrict__ b1,
                                                 const float* __restrict__ b3) {
    extern __shared__ __half smh[];
    __half* sh_h = smh;              // [64][72]
    __half* sh_w = smh + 64 * 72;    // [3][64 k][72 n]
    int tid = threadIdx.x;
    int nbase = blockIdx.x * 64;

    // h tile: 64 rows x 64 halves, straight 16B copies
    for (int i = tid; i < 512; i += 256) {
        int node = i >> 3, k8 = (i & 7) * 8;
        int gn = nbase + node;
        uint4 v = make_uint4(0u, 0u, 0u, 0u);
        if (gn < NN) v = *(const uint4*)&g_hh[gn * 64 + k8];
        *(uint4*)&sh_h[node * 72 + k8] = v;
    }
    // W tiles: fp16 copy from g_Wh (8 halves per iteration)
    const __half* wsrc = &g_Wh[layer * 3 * 4096];
    for (int i = tid; i < 1536; i += 256) {
        int idx = i * 8;
        int m = idx >> 12, rem = idx & 4095;
        int k = rem >> 6, n8 = rem & 63;
        uint4 v = *(const uint4*)&wsrc[idx];
        *(uint4*)&sh_w[m * 4608 + k * 72 + n8] = v;
    }
    __syncthreads();

    int w = tid >> 5, lane = tid & 31;
    int rowW = w & 3, colH = w >> 2;
    int gid = lane >> 2, tid4 = lane & 3;

    float acc[12][4];
#pragma unroll
    for (int t = 0; t < 12; t++) {
        acc[t][0] = 0.f; acc[t][1] = 0.f; acc[t][2] = 0.f; acc[t][3] = 0.f;
    }

    uint32_t sbase = smem_u32(smh);
    uint32_t hbase = sbase;              // h at offset 0
    uint32_t wbase = sbase + 64 * 72 * 2;
    int lrow = lane & 15, lhi = lane >> 4;

#pragma unroll
    for (int kt = 0; kt < 4; kt++) {
        int k0 = kt * 16;
        uint32_t a0, a1, a2, a3;
        uint32_t aaddr = hbase + ((rowW * 16 + lrow) * 72 + k0 + lhi * 8) * 2;
        asm volatile("ldmatrix.sync.aligned.m8n8.x4.shared.b16 {%0,%1,%2,%3}, [%4];"
                     : "=r"(a0), "=r"(a1), "=r"(a2), "=r"(a3) : "r"(aaddr));
#pragma unroll
        for (int m = 0; m < 3; m++) {
#pragma unroll
            for (int tp = 0; tp < 2; tp++) {           // pair of n8 tiles
                int n0 = colH * 32 + tp * 16;
                // x4.trans: mats {k0-7,n0}, {k8-15,n0}, {k0-7,n0+8}, {k8-15,n0+8}
                uint32_t b0, b1r, b2, b3r;
                uint32_t baddr = wbase + (m * 4608 + (k0 + lrow) * 72 + n0 + lhi * 8) * 2;
                asm volatile("ldmatrix.sync.aligned.m8n8.x4.trans.shared.b16 {%0,%1,%2,%3}, [%4];"
                             : "=r"(b0), "=r"(b1r), "=r"(b2), "=r"(b3r) : "r"(baddr));
                float* c0 = acc[m * 4 + tp * 2];
                float* c1 = acc[m * 4 + tp * 2 + 1];
                asm volatile(
                    "mma.sync.aligned.m16n8k16.row.col.f32.f16.f16.f32 "
                    "{%0,%1,%2,%3}, {%4,%5,%6,%7}, {%8,%9}, {%0,%1,%2,%3};"
                    : "+f"(c0[0]), "+f"(c0[1]), "+f"(c0[2]), "+f"(c0[3])
                    : "r"(a0), "r"(a1), "r"(a2), "r"(a3), "r"(b0), "r"(b1r));
                asm volatile(
                    "mma.sync.aligned.m16n8k16.row.col.f32.f16.f16.f32 "
                    "{%0,%1,%2,%3}, {%4,%5,%6,%7}, {%8,%9}, {%0,%1,%2,%3};"
                    : "+f"(c1[0]), "+f"(c1[1]), "+f"(c1[2]), "+f"(c1[3])
                    : "r"(a0), "r"(a1), "r"(a2), "r"(a3), "r"(b2), "r"(b3r));
            }
        }
    }

    int r1 = nbase + rowW * 16 + gid;
    int r2 = r1 + 8;
#pragma unroll
    for (int tt = 0; tt < 4; tt++) {
        int c = colH * 32 + tt * 8 + tid4 * 2;
        float2 b1v = *(const float2*)&b1[c];
        float2 b3v = *(const float2*)&b3[c];
        float* aW1 = acc[tt];
        float* aW2 = acc[4 + tt];
        float* aW3 = acc[8 + tt];
        if (r1 < NN) {
            *(__half2*)&g_Ah[r1 * 64 + c] = __floats2half2_rn(aW1[0] + b1v.x, aW1[1] + b1v.y);
            *(__half2*)&g_Bh[r1 * 64 + c] = __floats2half2_rn(aW2[0], aW2[1]);
            *(__half2*)&g_Ch[r1 * 64 + c] = __floats2half2_rn(aW3[0] + b3v.x, aW3[1] + b3v.y);
        }
        if (r2 < NN) {
            *(__half2*)&g_Ah[r2 * 64 + c] = __floats2half2_rn(aW1[2] + b1v.x, aW1[3] + b1v.y);
            *(__half2*)&g_Bh[r2 * 64 + c] = __floats2half2_rn(aW2[2], aW2[3]);
            *(__half2*)&g_Ch[r2 * 64 + c] = __floats2half2_rn(aW3[2] + b3v.x, aW3[3] + b3v.y);
        }
    }
}

// -------- gather: h = relu( sum_e w*A[src] + C - wsum*B ), warp per node -----
// LAST layer also computes node attention natt.
template <bool LAST>
__global__ void k_gather() {
    int gt = blockIdx.x * 256 + threadIdx.x;
    int node = gt >> 5, lane = gt & 31;
    if (node >= NN) return;
    int s = g_rs[node];
    int len = g_cnt[node];
    int e = s + len;
    int loff = lane * 2;
    float ax0 = 0.f, ay0 = 0.f, ax1 = 0.f, ay1 = 0.f;
    float wsum = 0.f, asum = 0.f;
    for (int base = s; base < e; base += 32) {
        int idx = base + lane;
        float4 ce = make_float4(0.f, 0.f, 0.f, 0.f);
        if (idx < e) ce = g_ce[idx];
        int sn = __float_as_int(ce.x);
        float wv = ce.y;
        if (LAST) asum += ce.z;
        int m = min(32, e - base);
        int mr = (m + 7) & ~7;
        for (int j = 0; j < mr; j += 8) {
            int s0 = __shfl_sync(0xffffffffu, sn, j);
            int s1 = __shfl_sync(0xffffffffu, sn, j + 1);
            int s2 = __shfl_sync(0xffffffffu, sn, j + 2);
            int s3 = __shfl_sync(0xffffffffu, sn, j + 3);
            int s4 = __shfl_sync(0xffffffffu, sn, j + 4);
            int s5 = __shfl_sync(0xffffffffu, sn, j + 5);
            int s6 = __shfl_sync(0xffffffffu, sn, j + 6);
            int s7 = __shfl_sync(0xffffffffu, sn, j + 7);
            float w0 = __shfl_sync(0xffffffffu, wv, j);
            float w1 = __shfl_sync(0xffffffffu, wv, j + 1);
            float w2 = __shfl_sync(0xffffffffu, wv, j + 2);
            float w3 = __shfl_sync(0xffffffffu, wv, j + 3);
            float w4 = __shfl_sync(0xffffffffu, wv, j + 4);
            float w5 = __shfl_sync(0xffffffffu, wv, j + 5);
            float w6 = __shfl_sync(0xffffffffu, wv, j + 6);
            float w7 = __shfl_sync(0xffffffffu, wv, j + 7);
            __half2 h0 = __ldg((const __half2*)&g_Ah[s0 * 64 + loff]);
            __half2 h1 = __ldg((const __half2*)&g_Ah[s1 * 64 + loff]);
            __half2 h2 = __ldg((const __half2*)&g_Ah[s2 * 64 + loff]);
            __half2 h3 = __ldg((const __half2*)&g_Ah[s3 * 64 + loff]);
            __half2 h4 = __ldg((const __half2*)&g_Ah[s4 * 64 + loff]);
            __half2 h5 = __ldg((const __half2*)&g_Ah[s5 * 64 + loff]);
            __half2 h6 = __ldg((const __half2*)&g_Ah[s6 * 64 + loff]);
            __half2 h7 = __ldg((const __half2*)&g_Ah[s7 * 64 + loff]);
            float2 v0 = __half22float2(h0);
            float2 v1 = __half22float2(h1);
            float2 v2 = __half22float2(h2);
            float2 v3 = __half22float2(h3);
            float2 v4 = __half22float2(h4);
            float2 v5 = __half22float2(h5);
            float2 v6 = __half22float2(h6);
            float2 v7 = __half22float2(h7);
            wsum += ((w0 + w1) + (w2 + w3)) + ((w4 + w5) + (w6 + w7));
            ax0 = fmaf(w0, v0.x, ax0); ay0 = fmaf(w0, v0.y, ay0);
            ax1 = fmaf(w1, v1.x, ax1); ay1 = fmaf(w1, v1.y, ay1);
            ax0 = fmaf(w2, v2.x, ax0); ay0 = fmaf(w2, v2.y, ay0);
            ax1 = fmaf(w3, v3.x, ax1); ay1 = fmaf(w3, v3.y, ay1);
            ax0 = fmaf(w4, v4.x, ax0); ay0 = fmaf(w4, v4.y, ay0);
            ax1 = fmaf(w5, v5.x, ax1); ay1 = fmaf(w5, v5.y, ay1);
            ax0 = fmaf(w6, v6.x, ax0); ay0 = fmaf(w6, v6.y, ay0);
            ax1 = fmaf(w7, v7.x, ax1); ay1 = fmaf(w7, v7.y, ay1);
        }
    }
    float2 bv = __half22float2(*(const __half2*)&g_Bh[node * 64 + loff]);
    float2 cv = __half22float2(*(const __half2*)&g_Ch[node * 64 + loff]);
    float hx = fmaxf(ax0 + ax1 + cv.x - wsum * bv.x, 0.f);
    float hy = fmaxf(ay0 + ay1 + cv.y - wsum * bv.y, 0.f);
    *(__half2*)&g_hh[node * 64 + loff] = __floats2half2_rn(hx, hy);
    if (LAST) {
#pragma unroll
        for (int o = 16; o > 0; o >>= 1)
            asum += __shfl_down_sync(0xffffffffu, asum, o);
        if (lane == 0) {
            float att_tot = asum + g_atts[node];
            float deg = (float)(len + g_degs[node]);
            g_natt[node] = att_tot / ((deg == 0.f) ? 1.f : deg);
        }
    }
}

// ------- fused pooling + MLP + scratch re-zero for next replay ---------------
__global__ void k_poolmlp(const int* __restrict__ batch,
                          const float* __restrict__ f1w, const float* __restrict__ f1b,
                          const float* __restrict__ f2w, const float* __restrict__ f2b,
                          float* __restrict__ out) {
    int g = blockIdx.x, tid = threadIdx.x;  // 128
    __shared__ int se[2];
    __shared__ float sacc[128], satt[128];
    __shared__ float sx[64], shh[128];

    // cleanup for next run (all readers of these arrays already finished)
    int tg = g * 128 + tid;  // 0..65535
    for (int i = tg; i < NN; i += NGR * 128) {
        g_cnt[i] = 0; g_atts[i] = 0.f; g_degs[i] = 0;
    }
    if (tg < 128) g_bsum[tg] = 0;
    if (tg == 0) g_tick = 0;

    if (tid < 2) {
        int key = g + tid;
        int lo = 0, hi = NN;
        while (lo < hi) {
            int mid = (lo + hi) >> 1;
            if (batch[mid] < key) lo = mid + 1; else hi = mid;
        }
        se[tid] = lo;
    }
    __syncthreads();
    int s = se[0], e = se[1];
    int c = tid & 63, part = tid >> 6;
    float acc = 0.f, att = 0.f;
    for (int i = s + part; i < e; i += 2) {
        float na = g_natt[i];
        acc = fmaf(__half2float(g_hh[i * 64 + c]), na, acc);
        att += na;
    }
    sacc[tid] = acc; satt[tid] = att;
    __syncthreads();
    if (tid < 64) {
        float a = sacc[tid] + sacc[tid + 64];
        float at = satt[0] + satt[64];
        float cnt = (float)(e - s);
        float gat = (at == 0.f) ? 1.f : at;
        float scale = cnt / (gat * fmaxf(cnt, 1.f));
        sx[tid] = a * scale;
    }
    __syncthreads();
    float a = f1b[tid];
#pragma unroll 8
    for (int k = 0; k < 64; k++) a = fmaf(sx[k], f1w[k * 128 + tid], a);
    shh[tid] = fmaxf(a, 0.f);
    __syncthreads();
    if (tid < 3) {
        float o = f2b[tid];
        for (int j = 0; j < 128; j++) o = fmaf(shh[j], f2w[j * 3 + tid], o);
        out[g * 3 + tid] = o;
    }
}

// ---------------- launch ----------------
extern "C" void kernel_launch(void* const* d_in, const int* in_sizes, int n_in,
                              void* d_out, int out_size) {
    const float* x     = (const float*)d_in[0];
    const int*   ei    = (const int*)d_in[1];
    const int*   batch = (const int*)d_in[2];
    const float* eattr = (const float*)d_in[3];
    const float* eatt  = (const float*)d_in[4];
    const float* embw  = (const float*)d_in[5];
    const float* embb  = (const float*)d_in[6];
    const float* l1w   = (const float*)d_in[7];
    const float* l1b   = (const float*)d_in[8];
    const float* l2w   = (const float*)d_in[9];
    const float* l3w   = (const float*)d_in[10];
    const float* l3b   = (const float*)d_in[11];
    const float* f1w   = (const float*)d_in[12];
    const float* f1b   = (const float*)d_in[13];
    const float* f2w   = (const float*)d_in[14];
    const float* f2b   = (const float*)d_in[15];
    float* out = (float*)d_out;

    const int smem_gemm = (64 * 72 + 3 * 64 * 72) * 2;  // 36864 B
    const int* src = ei;
    const int* dst = ei + NE;

    k_initedge<<<(NN * 32 + 255) / 256, 256>>>(x, embw, embb, dst, l1w, l2w, l3w);
    k_scan<<<(NN + 1023) / 1024, 256>>>();
    k_fill<<<(NE / 4 + 255) / 256, 256>>>(src, dst, eattr, eatt);

    for (int l = 0; l < 3; l++) {
        k_gemm<<<(NN + 63) / 64, 256, smem_gemm>>>(l, l1b + l * 64, l3b + l * 64);
        if (l < 2)
            k_gather<false><<<(NN * 32 + 255) / 256, 256>>>();
        else
            k_gather<true><<<(NN * 32 + 255) / 256, 256>>>();
    }

    k_poolmlp<<<NGR, 128>>>(batch, f1w, f1b, f2w, f2b, out);
}

// round 15
// speedup vs baseline: 1.0130x; 1.0130x over previous
#include <cuda_runtime.h>
#include <cuda_fp16.h>
#include <cstdint>

#define NN 100000
#define NE 1000000
#define NGR 512
#define GTILES 1563   // (NN+63)/64

// ---------------- scratch ----------------
// NOTE: g_cnt/g_atts/g_degs/g_bsum/g_tick are zeroed at the TAIL of k_poolmlp
// (previous run) -- first run relies on static zero-init of device globals.
__device__ float g_atts[NN];      // src-side attention sum (atomic)
__device__ int   g_degs[NN];      // src-side degree (atomic)
__device__ float g_natt[NN];      // final node attention (written by last gather)
__device__ int   g_cnt[NN];       // in-degree (CSR row counts)
__device__ int   g_rs[NN];        // CSR row start
__device__ int   g_cur[NN];       // CSR fill cursor
__device__ int   g_bsum[128];     // chained-scan flags
__device__ int   g_tick;
__device__ float4 g_ce[NE];       // CSR: {src_as_bits, w, atten, pad}
__device__ __half g_Wh[9 * 4096]; // fp16 weights: [layer][mat(W1,W2,W3)][64k][64n]
__device__ __half g_hh[NN * 64];  // h in fp16
__device__ __half g_Ah[NN * 64];  // A = h@W1+b1
__device__ __half g_Bh[NN * 64];  // B = h@W2
__device__ __half g_Ch[NN * 64];  // C = h@W3+b3

__device__ __forceinline__ uint32_t smem_u32(const void* p) {
    uint32_t a;
    asm("{ .reg .u64 t; cvta.to.shared.u64 t, %1; cvt.u32.u64 %0, t; }" : "=r"(a) : "l"(p));
    return a;
}

// ------- init: node embedding + dst histogram + fp16 weight precompute -------
__global__ void k_initedge(const float* __restrict__ x, const float* __restrict__ w,
                           const float* __restrict__ b, const int* __restrict__ dst,
                           const float* __restrict__ l1w, const float* __restrict__ l2w,
                           const float* __restrict__ l3w) {
    int gid = blockIdx.x * 256 + threadIdx.x;
    if (gid < NE / 4) {
        int4 d = *(const int4*)&dst[gid * 4];
        atomicAdd(&g_cnt[d.x], 1); atomicAdd(&g_cnt[d.y], 1);
        atomicAdd(&g_cnt[d.z], 1); atomicAdd(&g_cnt[d.w], 1);
    }
    // fp16 weight conversion: 3 arrays x 12288 floats -> g_Wh[l][mat][4096]
    if (gid < 9216) {
        int i4 = gid * 4;
        int arr = i4 / 12288;
        int off = i4 % 12288;
        int l = off >> 12, loff = off & 4095;
        const float* srcp = (arr == 0) ? l1w : ((arr == 1) ? l2w : l3w);
        float4 v = *(const float4*)&srcp[off];
        __half2 lo = __floats2half2_rn(v.x, v.y);
        __half2 hi = __floats2half2_rn(v.z, v.w);
        uint2 pk = make_uint2(*(uint32_t*)&lo, *(uint32_t*)&hi);
        *(uint2*)&g_Wh[(l * 3 + arr) * 4096 + loff] = pk;
    }
    if (gid < NN * 32) {
        int i = gid >> 5, c = (gid & 31) * 2;
        float4 xv = *(const float4*)&x[i * 4];
        float h0 = b[c]     + xv.x * w[c]     + xv.y * w[64 + c]     + xv.z * w[128 + c]     + xv.w * w[192 + c];
        float h1 = b[c + 1] + xv.x * w[c + 1] + xv.y * w[64 + c + 1] + xv.z * w[128 + c + 1] + xv.w * w[192 + c + 1];
        *(__half2*)&g_hh[i * 64 + c] = __floats2half2_rn(h0, h1);
    }
}

// ---------------- single-pass chained exclusive scan: g_cnt -> g_rs, g_cur ----
__global__ void k_scan() {
    __shared__ int sm_t, sm_prev, wsum[8];
    int tid = threadIdx.x;
    if (tid == 0) sm_t = atomicAdd(&g_tick, 1);
    __syncthreads();
    int t = sm_t;
    int base = t * 1024 + tid * 4;
    int v0 = 0, v1 = 0, v2 = 0, v3 = 0;
    if (base + 3 < NN) {
        int4 q = *(const int4*)&g_cnt[base];
        v0 = q.x; v1 = q.y; v2 = q.z; v3 = q.w;
    } else {
        if (base < NN)     v0 = g_cnt[base];
        if (base + 1 < NN) v1 = g_cnt[base + 1];
        if (base + 2 < NN) v2 = g_cnt[base + 2];
        if (base + 3 < NN) v3 = g_cnt[base + 3];
    }
    int sloc = v0 + v1 + v2 + v3;
    int x = sloc;
#pragma unroll
    for (int o = 1; o < 32; o <<= 1) {
        int y = __shfl_up_sync(0xffffffffu, x, o);
        if ((tid & 31) >= o) x += y;
    }
    if ((tid & 31) == 31) wsum[tid >> 5] = x;
    __syncthreads();
    if (tid < 8) {
        int y = wsum[tid];
#pragma unroll
        for (int o = 1; o < 8; o <<= 1) {
            int z = __shfl_up_sync(0xffu, y, o);
            if (tid >= o) y += z;
        }
        wsum[tid] = y;
    }
    __syncthreads();
    int woff = (tid >= 32) ? wsum[(tid >> 5) - 1] : 0;
    int excl = x - sloc + woff;
    int total = wsum[7];
    if (tid == 0) {
        int prev = 0;
        if (t > 0) {
            int v;
            while ((v = atomicAdd(&g_bsum[t - 1], 0)) == 0) {}
            prev = v - 1;
        }
        atomicExch(&g_bsum[t], prev + total + 1);
        sm_prev = prev;
    }
    __syncthreads();
    int off = sm_prev + excl;
    if (base < NN)     { g_rs[base]     = off;                g_cur[base]     = off; }
    if (base + 1 < NN) { g_rs[base + 1] = off + v0;           g_cur[base + 1] = off + v0; }
    if (base + 2 < NN) { g_rs[base + 2] = off + v0 + v1;      g_cur[base + 2] = off + v0 + v1; }
    if (base + 3 < NN) { g_rs[base + 3] = off + v0 + v1 + v2; g_cur[base + 3] = off + v0 + v1 + v2; }
}

// ---------------- CSR fill + src-side atomics (4 edges/thread, 16B records) --
__global__ void k_fill(const int* __restrict__ src, const int* __restrict__ dst,
                       const float* __restrict__ attr, const float* __restrict__ atten) {
    int e4 = blockIdx.x * 256 + threadIdx.x;
    if (e4 * 4 >= NE) return;
    int4 s = *(const int4*)&src[e4 * 4];
    int4 d = *(const int4*)&dst[e4 * 4];
    float4 ar = *(const float4*)&attr[e4 * 4];
    float4 at = *(const float4*)&atten[e4 * 4];
    int p0 = atomicAdd(&g_cur[d.x], 1);
    int p1 = atomicAdd(&g_cur[d.y], 1);
    int p2 = atomicAdd(&g_cur[d.z], 1);
    int p3 = atomicAdd(&g_cur[d.w], 1);
    g_ce[p0] = make_float4(__int_as_float(s.x), ar.x * at.x, at.x, 0.f);
    g_ce[p1] = make_float4(__int_as_float(s.y), ar.y * at.y, at.y, 0.f);
    g_ce[p2] = make_float4(__int_as_float(s.z), ar.z * at.z, at.z, 0.f);
    g_ce[p3] = make_float4(__int_as_float(s.w), ar.w * at.w, at.w, 0.f);
    atomicAdd(&g_atts[s.x], at.x); atomicAdd(&g_atts[s.y], at.y);
    atomicAdd(&g_atts[s.z], at.z); atomicAdd(&g_atts[s.w], at.w);
    atomicAdd(&g_degs[s.x], 1);    atomicAdd(&g_degs[s.y], 1);
    atomicAdd(&g_degs[s.z], 1);    atomicAdd(&g_degs[s.w], 1);
}

// -------- layer GEMM via fp16 mma.m16n8k16: A=h@W1+b1, B=h@W2, C=h@W3+b3 -----
// Multi-tile: each block loads W once, loops over h tiles with grid stride.
__global__ void __launch_bounds__(256, 3) k_gemm(int layer,
                                                 const float* __restrict__ b1,
                                                 const float* __restrict__ b3) {
    extern __shared__ __half smh[];
    __half* sh_h = smh;              // [64][72]
    __half* sh_w = smh + 64 * 72;    // [3][64 k][72 n]
    int tid = threadIdx.x;

    // W tiles: fp16 copy from g_Wh, once per block
    const __half* wsrc = &g_Wh[layer * 3 * 4096];
    for (int i = tid; i < 1536; i += 256) {
        int idx = i * 8;
        int m = idx >> 12, rem = idx & 4095;
        int k = rem >> 6, n8 = rem & 63;
        uint4 v = *(const uint4*)&wsrc[idx];
        *(uint4*)&sh_w[m * 4608 + k * 72 + n8] = v;
    }

    int w = tid >> 5, lane = tid & 31;
    int rowW = w & 3, colH = w >> 2;
    int gid = lane >> 2, tid4 = lane & 3;
    int lrow = lane & 15, lhi = lane >> 4;

    uint32_t sbase = smem_u32(smh);
    uint32_t hbase = sbase;
    uint32_t wbase = sbase + 64 * 72 * 2;
    uint32_t aaddr = hbase + ((rowW * 16 + lrow) * 72 + lhi * 8) * 2;

    for (int tile = blockIdx.x; tile < GTILES; tile += gridDim.x) {
        int nbase = tile * 64;
        __syncthreads();  // protect sh_h from previous iteration's readers
        for (int i = tid; i < 512; i += 256) {
            int node = i >> 3, k8 = (i & 7) * 8;
            int gn = nbase + node;
            uint4 v = make_uint4(0u, 0u, 0u, 0u);
            if (gn < NN) v = *(const uint4*)&g_hh[gn * 64 + k8];
            *(uint4*)&sh_h[node * 72 + k8] = v;
        }
        __syncthreads();

        float acc[12][4];
#pragma unroll
        for (int t = 0; t < 12; t++) {
            acc[t][0] = 0.f; acc[t][1] = 0.f; acc[t][2] = 0.f; acc[t][3] = 0.f;
        }

#pragma unroll
        for (int kt = 0; kt < 4; kt++) {
            int k0 = kt * 16;
            uint32_t a0, a1, a2, a3;
            asm volatile("ldmatrix.sync.aligned.m8n8.x4.shared.b16 {%0,%1,%2,%3}, [%4];"
                         : "=r"(a0), "=r"(a1), "=r"(a2), "=r"(a3) : "r"(aaddr + k0 * 2));
#pragma unroll
            for (int m = 0; m < 3; m++) {
#pragma unroll
                for (int tt = 0; tt < 4; tt++) {
                    int n0 = colH * 32 + tt * 8;
                    uint32_t b0, b1r;
                    uint32_t baddr = wbase + (m * 4608 + (k0 + lrow) * 72 + n0) * 2;
                    asm volatile("ldmatrix.sync.aligned.m8n8.x2.trans.shared.b16 {%0,%1}, [%2];"
                                 : "=r"(b0), "=r"(b1r) : "r"(baddr));
                    float* c = acc[m * 4 + tt];
                    asm volatile(
                        "mma.sync.aligned.m16n8k16.row.col.f32.f16.f16.f32 "
                        "{%0,%1,%2,%3}, {%4,%5,%6,%7}, {%8,%9}, {%0,%1,%2,%3};"
                        : "+f"(c[0]), "+f"(c[1]), "+f"(c[2]), "+f"(c[3])
                        : "r"(a0), "r"(a1), "r"(a2), "r"(a3), "r"(b0), "r"(b1r));
                }
            }
        }

        int r1 = nbase + rowW * 16 + gid;
        int r2 = r1 + 8;
#pragma unroll
        for (int tt = 0; tt < 4; tt++) {
            int c = colH * 32 + tt * 8 + tid4 * 2;
            float2 b1v = *(const float2*)&b1[c];
            float2 b3v = *(const float2*)&b3[c];
            float* aW1 = acc[tt];
            float* aW2 = acc[4 + tt];
            float* aW3 = acc[8 + tt];
            if (r1 < NN) {
                *(__half2*)&g_Ah[r1 * 64 + c] = __floats2half2_rn(aW1[0] + b1v.x, aW1[1] + b1v.y);
                *(__half2*)&g_Bh[r1 * 64 + c] = __floats2half2_rn(aW2[0], aW2[1]);
                *(__half2*)&g_Ch[r1 * 64 + c] = __floats2half2_rn(aW3[0] + b3v.x, aW3[1] + b3v.y);
            }
            if (r2 < NN) {
                *(__half2*)&g_Ah[r2 * 64 + c] = __floats2half2_rn(aW1[2] + b1v.x, aW1[3] + b1v.y);
                *(__half2*)&g_Bh[r2 * 64 + c] = __floats2half2_rn(aW2[2], aW2[3]);
                *(__half2*)&g_Ch[r2 * 64 + c] = __floats2half2_rn(aW3[2] + b3v.x, aW3[3] + b3v.y);
            }
        }
    }
}

// -------- gather: h = relu( sum_e w*A[src] + C - wsum*B ), warp per node -----
// LAST layer also computes node attention natt.
template <bool LAST>
__global__ void k_gather() {
    int gt = blockIdx.x * 256 + threadIdx.x;
    int node = gt >> 5, lane = gt & 31;
    if (node >= NN) return;
    int s = g_rs[node];
    int len = g_cnt[node];
    int e = s + len;
    int loff = lane * 2;
    float ax0 = 0.f, ay0 = 0.f, ax1 = 0.f, ay1 = 0.f;
    float wsum = 0.f, asum = 0.f;
    for (int base = s; base < e; base += 32) {
        int idx = base + lane;
        float4 ce = make_float4(0.f, 0.f, 0.f, 0.f);
        if (idx < e) ce = g_ce[idx];
        int sn = __float_as_int(ce.x);
        float wv = ce.y;
        if (LAST) asum += ce.z;
        int m = min(32, e - base);
        int mr = (m + 7) & ~7;
        for (int j = 0; j < mr; j += 8) {
            int s0 = __shfl_sync(0xffffffffu, sn, j);
            int s1 = __shfl_sync(0xffffffffu, sn, j + 1);
            int s2 = __shfl_sync(0xffffffffu, sn, j + 2);
            int s3 = __shfl_sync(0xffffffffu, sn, j + 3);
            int s4 = __shfl_sync(0xffffffffu, sn, j + 4);
            int s5 = __shfl_sync(0xffffffffu, sn, j + 5);
            int s6 = __shfl_sync(0xffffffffu, sn, j + 6);
            int s7 = __shfl_sync(0xffffffffu, sn, j + 7);
            float w0 = __shfl_sync(0xffffffffu, wv, j);
            float w1 = __shfl_sync(0xffffffffu, wv, j + 1);
            float w2 = __shfl_sync(0xffffffffu, wv, j + 2);
            float w3 = __shfl_sync(0xffffffffu, wv, j + 3);
            float w4 = __shfl_sync(0xffffffffu, wv, j + 4);
            float w5 = __shfl_sync(0xffffffffu, wv, j + 5);
            float w6 = __shfl_sync(0xffffffffu, wv, j + 6);
            float w7 = __shfl_sync(0xffffffffu, wv, j + 7);
            __half2 h0 = __ldg((const __half2*)&g_Ah[s0 * 64 + loff]);
            __half2 h1 = __ldg((const __half2*)&g_Ah[s1 * 64 + loff]);
            __half2 h2 = __ldg((const __half2*)&g_Ah[s2 * 64 + loff]);
            __half2 h3 = __ldg((const __half2*)&g_Ah[s3 * 64 + loff]);
            __half2 h4 = __ldg((const __half2*)&g_Ah[s4 * 64 + loff]);
            __half2 h5 = __ldg((const __half2*)&g_Ah[s5 * 64 + loff]);
            __half2 h6 = __ldg((const __half2*)&g_Ah[s6 * 64 + loff]);
            __half2 h7 = __ldg((const __half2*)&g_Ah[s7 * 64 + loff]);
            float2 v0 = __half22float2(h0);
            float2 v1 = __half22float2(h1);
            float2 v2 = __half22float2(h2);
            float2 v3 = __half22float2(h3);
            float2 v4 = __half22float2(h4);
            float2 v5 = __half22float2(h5);
            float2 v6 = __half22float2(h6);
            float2 v7 = __half22float2(h7);
            wsum += ((w0 + w1) + (w2 + w3)) + ((w4 + w5) + (w6 + w7));
            ax0 = fmaf(w0, v0.x, ax0); ay0 = fmaf(w0, v0.y, ay0);
            ax1 = fmaf(w1, v1.x, ax1); ay1 = fmaf(w1, v1.y, ay1);
            ax0 = fmaf(w2, v2.x, ax0); ay0 = fmaf(w2, v2.y, ay0);
            ax1 = fmaf(w3, v3.x, ax1); ay1 = fmaf(w3, v3.y, ay1);
            ax0 = fmaf(w4, v4.x, ax0); ay0 = fmaf(w4, v4.y, ay0);
            ax1 = fmaf(w5, v5.x, ax1); ay1 = fmaf(w5, v5.y, ay1);
            ax0 = fmaf(w6, v6.x, ax0); ay0 = fmaf(w6, v6.y, ay0);
            ax1 = fmaf(w7, v7.x, ax1); ay1 = fmaf(w7, v7.y, ay1);
        }
    }
    float2 bv = __half22float2(*(const __half2*)&g_Bh[node * 64 + loff]);
    float2 cv = __half22float2(*(const __half2*)&g_Ch[node * 64 + loff]);
    float hx = fmaxf(ax0 + ax1 + cv.x - wsum * bv.x, 0.f);
    float hy = fmaxf(ay0 + ay1 + cv.y - wsum * bv.y, 0.f);
    *(__half2*)&g_hh[node * 64 + loff] = __floats2half2_rn(hx, hy);
    if (LAST) {
#pragma unroll
        for (int o = 16; o > 0; o >>= 1)
            asum += __shfl_down_sync(0xffffffffu, asum, o);
        if (lane == 0) {
            float att_tot = asum + g_atts[node];
            float deg = (float)(len + g_degs[node]);
            g_natt[node] = att_tot / ((deg == 0.f) ? 1.f : deg);
        }
    }
}

// ------- fused pooling + MLP + scratch re-zero for next replay ---------------
__global__ void k_poolmlp(const int* __restrict__ batch,
                          const float* __restrict__ f1w, const float* __restrict__ f1b,
                          const float* __restrict__ f2w, const float* __restrict__ f2b,
                          float* __restrict__ out) {
    int g = blockIdx.x, tid = threadIdx.x;  // 128
    __shared__ int se[2];
    __shared__ float sacc[128], satt[128];
    __shared__ float sx[64], shh[128];

    // cleanup for next run (all readers of these arrays already finished)
    int tg = g * 128 + tid;  // 0..65535
    for (int i = tg; i < NN; i += NGR * 128) {
        g_cnt[i] = 0; g_atts[i] = 0.f; g_degs[i] = 0;
    }
    if (tg < 128) g_bsum[tg] = 0;
    if (tg == 0) g_tick = 0;

    if (tid < 2) {
        int key = g + tid;
        int lo = 0, hi = NN;
        while (lo < hi) {
            int mid = (lo + hi) >> 1;
            if (batch[mid] < key) lo = mid + 1; else hi = mid;
        }
        se[tid] = lo;
    }
    __syncthreads();
    int s = se[0], e = se[1];
    int c = tid & 63, part = tid >> 6;
    float acc = 0.f, att = 0.f;
    for (int i = s + part; i < e; i += 2) {
        float na = g_natt[i];
        acc = fmaf(__half2float(g_hh[i * 64 + c]), na, acc);
        att += na;
    }
    sacc[tid] = acc; satt[tid] = att;
    __syncthreads();
    if (tid < 64) {
        float a = sacc[tid] + sacc[tid + 64];
        float at = satt[0] + satt[64];
        float cnt = (float)(e - s);
        float gat = (at == 0.f) ? 1.f : at;
        float scale = cnt / (gat * fmaxf(cnt, 1.f));
        sx[tid] = a * scale;
    }
    __syncthreads();
    float a = f1b[tid];
#pragma unroll 8
    for (int k = 0; k < 64; k++) a = fmaf(sx[k], f1w[k * 128 + tid], a);
    shh[tid] = fmaxf(a, 0.f);
    __syncthreads();
    if (tid < 3) {
        float o = f2b[tid];
        for (int j = 0; j < 128; j++) o = fmaf(shh[j], f2w[j * 3 + tid], o);
        out[g * 3 + tid] = o;
    }
}

// ---------------- launch ----------------
extern "C" void kernel_launch(void* const* d_in, const int* in_sizes, int n_in,
                              void* d_out, int out_size) {
    const float* x     = (const float*)d_in[0];
    const int*   ei    = (const int*)d_in[1];
    const int*   batch = (const int*)d_in[2];
    const float* eattr = (const float*)d_in[3];
    const float* eatt  = (const float*)d_in[4];
    const float* embw  = (const float*)d_in[5];
    const float* embb  = (const float*)d_in[6];
    const float* l1w   = (const float*)d_in[7];
    const float* l1b   = (const float*)d_in[8];
    const float* l2w   = (const float*)d_in[9];
    const float* l3w   = (const float*)d_in[10];
    const float* l3b   = (const float*)d_in[11];
    const float* f1w   = (const float*)d_in[12];
    const float* f1b   = (const float*)d_in[13];
    const float* f2w   = (const float*)d_in[14];
    const float* f2b   = (const float*)d_in[15];
    float* out = (float*)d_out;

    const int smem_gemm = (64 * 72 + 3 * 64 * 72) * 2;  // 36864 B
    const int* src = ei;
    const int* dst = ei + NE;

    int sms = 148;
    cudaDeviceGetAttribute(&sms, cudaDevAttrMultiProcessorCount, 0);
    int gemm_blocks = sms * 3;

    k_initedge<<<(NN * 32 + 255) / 256, 256>>>(x, embw, embb, dst, l1w, l2w, l3w);
    k_scan<<<(NN + 1023) / 1024, 256>>>();
    k_fill<<<(NE / 4 + 255) / 256, 256>>>(src, dst, eattr, eatt);

    for (int l = 0; l < 3; l++) {
        k_gemm<<<gemm_blocks, 256, smem_gemm>>>(l, l1b + l * 64, l3b + l * 64);
        if (l < 2)
            k_gather<false><<<(NN * 32 + 255) / 256, 256>>>();
        else
            k_gather<true><<<(NN * 32 + 255) / 256, 256>>>();
    }

    k_poolmlp<<<NGR, 128>>>(batch, f1w, f1b, f2w, f2b, out);
}

// round 16
// speedup vs baseline: 1.0817x; 1.0678x over previous
#include <cuda_runtime.h>
#include <cuda_fp16.h>
#include <cstdint>

#define NN 100000
#define NE 1000000
#define NGR 512
#define GTILES 1563   // (NN+63)/64

// ---------------- scratch ----------------
// NOTE: g_cnt/g_atts/g_degs/g_bsum/g_tick are zeroed at the TAIL of k_poolmlp
// (previous run) -- first run relies on static zero-init of device globals.
__device__ float g_atts[NN];      // src-side attention sum (atomic)
__device__ int   g_degs[NN];      // src-side degree (atomic)
__device__ float g_natt[NN];      // final node attention (written by last gather)
__device__ int   g_cnt[NN];       // in-degree (CSR row counts)
__device__ int   g_rs[NN];        // CSR row start
__device__ int   g_cur[NN];       // CSR fill cursor
__device__ int   g_bsum[128];     // chained-scan flags
__device__ int   g_tick;
__device__ float4 g_ce[NE];       // CSR: {src_as_bits, w, atten, pad}
__device__ __half g_Wh[9 * 4096]; // fp16 weights: [layer][mat(W1,W2,W3)][64k][64n]
__device__ __half g_hh[NN * 64];  // h in fp16
__device__ __half g_Ah[NN * 64];  // A = h@W1+b1
__device__ __half g_Bh[NN * 64];  // B = h@W2
__device__ __half g_Ch[NN * 64];  // C = h@W3+b3

__device__ __forceinline__ uint32_t smem_u32(const void* p) {
    uint32_t a;
    asm("{ .reg .u64 t; cvta.to.shared.u64 t, %1; cvt.u32.u64 %0, t; }" : "=r"(a) : "l"(p));
    return a;
}

// ------- init: node embedding + dst histogram + fp16 weight precompute -------
__global__ void k_initedge(const float* __restrict__ x, const float* __restrict__ w,
                           const float* __restrict__ b, const int* __restrict__ dst,
                           const float* __restrict__ l1w, const float* __restrict__ l2w,
                           const float* __restrict__ l3w) {
    int gid = blockIdx.x * 256 + threadIdx.x;
    if (gid < NE / 4) {
        int4 d = *(const int4*)&dst[gid * 4];
        atomicAdd(&g_cnt[d.x], 1); atomicAdd(&g_cnt[d.y], 1);
        atomicAdd(&g_cnt[d.z], 1); atomicAdd(&g_cnt[d.w], 1);
    }
    if (gid < 9216) {
        int i4 = gid * 4;
        int arr = i4 / 12288;
        int off = i4 % 12288;
        int l = off >> 12, loff = off & 4095;
        const float* srcp = (arr == 0) ? l1w : ((arr == 1) ? l2w : l3w);
        float4 v = *(const float4*)&srcp[off];
        __half2 lo = __floats2half2_rn(v.x, v.y);
        __half2 hi = __floats2half2_rn(v.z, v.w);
        uint2 pk = make_uint2(*(uint32_t*)&lo, *(uint32_t*)&hi);
        *(uint2*)&g_Wh[(l * 3 + arr) * 4096 + loff] = pk;
    }
    if (gid < NN * 32) {
        int i = gid >> 5, c = (gid & 31) * 2;
        float4 xv = *(const float4*)&x[i * 4];
        float h0 = b[c]     + xv.x * w[c]     + xv.y * w[64 + c]     + xv.z * w[128 + c]     + xv.w * w[192 + c];
        float h1 = b[c + 1] + xv.x * w[c + 1] + xv.y * w[64 + c + 1] + xv.z * w[128 + c + 1] + xv.w * w[192 + c + 1];
        *(__half2*)&g_hh[i * 64 + c] = __floats2half2_rn(h0, h1);
    }
}

// ---------------- single-pass chained exclusive scan: g_cnt -> g_rs, g_cur ----
__global__ void k_scan() {
    __shared__ int sm_t, sm_prev, wsum[8];
    int tid = threadIdx.x;
    if (tid == 0) sm_t = atomicAdd(&g_tick, 1);
    __syncthreads();
    int t = sm_t;
    int base = t * 1024 + tid * 4;
    int v0 = 0, v1 = 0, v2 = 0, v3 = 0;
    if (base + 3 < NN) {
        int4 q = *(const int4*)&g_cnt[base];
        v0 = q.x; v1 = q.y; v2 = q.z; v3 = q.w;
    } else {
        if (base < NN)     v0 = g_cnt[base];
        if (base + 1 < NN) v1 = g_cnt[base + 1];
        if (base + 2 < NN) v2 = g_cnt[base + 2];
        if (base + 3 < NN) v3 = g_cnt[base + 3];
    }
    int sloc = v0 + v1 + v2 + v3;
    int x = sloc;
#pragma unroll
    for (int o = 1; o < 32; o <<= 1) {
        int y = __shfl_up_sync(0xffffffffu, x, o);
        if ((tid & 31) >= o) x += y;
    }
    if ((tid & 31) == 31) wsum[tid >> 5] = x;
    __syncthreads();
    if (tid < 8) {
        int y = wsum[tid];
#pragma unroll
        for (int o = 1; o < 8; o <<= 1) {
            int z = __shfl_up_sync(0xffu, y, o);
            if (tid >= o) y += z;
        }
        wsum[tid] = y;
    }
    __syncthreads();
    int woff = (tid >= 32) ? wsum[(tid >> 5) - 1] : 0;
    int excl = x - sloc + woff;
    int total = wsum[7];
    if (tid == 0) {
        int prev = 0;
        if (t > 0) {
            int v;
            while ((v = atomicAdd(&g_bsum[t - 1], 0)) == 0) {}
            prev = v - 1;
        }
        atomicExch(&g_bsum[t], prev + total + 1);
        sm_prev = prev;
    }
    __syncthreads();
    int off = sm_prev + excl;
    if (base < NN)     { g_rs[base]     = off;                g_cur[base]     = off; }
    if (base + 1 < NN) { g_rs[base + 1] = off + v0;           g_cur[base + 1] = off + v0; }
    if (base + 2 < NN) { g_rs[base + 2] = off + v0 + v1;      g_cur[base + 2] = off + v0 + v1; }
    if (base + 3 < NN) { g_rs[base + 3] = off + v0 + v1 + v2; g_cur[base + 3] = off + v0 + v1 + v2; }
}

// ---------------- CSR fill + src-side atomics (4 edges/thread, 16B records) --
__global__ void k_fill(const int* __restrict__ src, const int* __restrict__ dst,
                       const float* __restrict__ attr, const float* __restrict__ atten) {
    int e4 = blockIdx.x * 256 + threadIdx.x;
    if (e4 * 4 >= NE) return;
    int4 s = *(const int4*)&src[e4 * 4];
    int4 d = *(const int4*)&dst[e4 * 4];
    float4 ar = *(const float4*)&attr[e4 * 4];
    float4 at = *(const float4*)&atten[e4 * 4];
    int p0 = atomicAdd(&g_cur[d.x], 1);
    int p1 = atomicAdd(&g_cur[d.y], 1);
    int p2 = atomicAdd(&g_cur[d.z], 1);
    int p3 = atomicAdd(&g_cur[d.w], 1);
    g_ce[p0] = make_float4(__int_as_float(s.x), ar.x * at.x, at.x, 0.f);
    g_ce[p1] = make_float4(__int_as_float(s.y), ar.y * at.y, at.y, 0.f);
    g_ce[p2] = make_float4(__int_as_float(s.z), ar.z * at.z, at.z, 0.f);
    g_ce[p3] = make_float4(__int_as_float(s.w), ar.w * at.w, at.w, 0.f);
    atomicAdd(&g_atts[s.x], at.x); atomicAdd(&g_atts[s.y], at.y);
    atomicAdd(&g_atts[s.z], at.z); atomicAdd(&g_atts[s.w], at.w);
    atomicAdd(&g_degs[s.x], 1);    atomicAdd(&g_degs[s.y], 1);
    atomicAdd(&g_degs[s.z], 1);    atomicAdd(&g_degs[s.w], 1);
}

// -------- layer GEMM via fp16 mma.m16n8k16: A=h@W1+b1, B=h@W2, C=h@W3+b3 -----
// Multi-tile, smem-staged coalesced epilogue.
__global__ void __launch_bounds__(256, 3) k_gemm(int layer,
                                                 const float* __restrict__ b1,
                                                 const float* __restrict__ b3) {
    extern __shared__ __half smh[];
    __half* sh_h = smh;              // [64][72] -- doubles as epilogue staging
    __half* sh_w = smh + 64 * 72;    // [3][64 k][72 n]
    int tid = threadIdx.x;

    // W tiles: fp16 copy from g_Wh, once per block
    const __half* wsrc = &g_Wh[layer * 3 * 4096];
    for (int i = tid; i < 1536; i += 256) {
        int idx = i * 8;
        int m = idx >> 12, rem = idx & 4095;
        int k = rem >> 6, n8 = rem & 63;
        uint4 v = *(const uint4*)&wsrc[idx];
        *(uint4*)&sh_w[m * 4608 + k * 72 + n8] = v;
    }

    int w = tid >> 5, lane = tid & 31;
    int rowW = w & 3, colH = w >> 2;
    int gid = lane >> 2, tid4 = lane & 3;
    int lrow = lane & 15, lhi = lane >> 4;

    uint32_t sbase = smem_u32(smh);
    uint32_t hbase = sbase;
    uint32_t wbase = sbase + 64 * 72 * 2;
    uint32_t aaddr = hbase + ((rowW * 16 + lrow) * 72 + lhi * 8) * 2;

    for (int tile = blockIdx.x; tile < GTILES; tile += gridDim.x) {
        int nbase = tile * 64;
        __syncthreads();  // protect sh_h staging from previous iteration readers
        for (int i = tid; i < 512; i += 256) {
            int node = i >> 3, k8 = (i & 7) * 8;
            int gn = nbase + node;
            uint4 v = make_uint4(0u, 0u, 0u, 0u);
            if (gn < NN) v = *(const uint4*)&g_hh[gn * 64 + k8];
            *(uint4*)&sh_h[node * 72 + k8] = v;
        }
        __syncthreads();

        float acc[12][4];
#pragma unroll
        for (int t = 0; t < 12; t++) {
            acc[t][0] = 0.f; acc[t][1] = 0.f; acc[t][2] = 0.f; acc[t][3] = 0.f;
        }

#pragma unroll
        for (int kt = 0; kt < 4; kt++) {
            int k0 = kt * 16;
            uint32_t a0, a1, a2, a3;
            asm volatile("ldmatrix.sync.aligned.m8n8.x4.shared.b16 {%0,%1,%2,%3}, [%4];"
                         : "=r"(a0), "=r"(a1), "=r"(a2), "=r"(a3) : "r"(aaddr + k0 * 2));
#pragma unroll
            for (int m = 0; m < 3; m++) {
#pragma unroll
                for (int tt = 0; tt < 4; tt++) {
                    int n0 = colH * 32 + tt * 8;
                    uint32_t b0, b1r;
                    uint32_t baddr = wbase + (m * 4608 + (k0 + lrow) * 72 + n0) * 2;
                    asm volatile("ldmatrix.sync.aligned.m8n8.x2.trans.shared.b16 {%0,%1}, [%2];"
                                 : "=r"(b0), "=r"(b1r) : "r"(baddr));
                    float* c = acc[m * 4 + tt];
                    asm volatile(
                        "mma.sync.aligned.m16n8k16.row.col.f32.f16.f16.f32 "
                        "{%0,%1,%2,%3}, {%4,%5,%6,%7}, {%8,%9}, {%0,%1,%2,%3};"
                        : "+f"(c[0]), "+f"(c[1]), "+f"(c[2]), "+f"(c[3])
                        : "r"(a0), "r"(a1), "r"(a2), "r"(a3), "r"(b0), "r"(b1r));
                }
            }
        }

        // staged epilogue: for each mat, STS fragments then coalesced STG.128
        int rl1 = rowW * 16 + gid;        // local rows
        int rl2 = rl1 + 8;
#pragma unroll
        for (int m = 0; m < 3; m++) {
            __syncthreads();  // sh_h reads (ldmatrix / prior STG) done
#pragma unroll
            for (int tt = 0; tt < 4; tt++) {
                int c = colH * 32 + tt * 8 + tid4 * 2;
                float* a = acc[m * 4 + tt];
                float bx = 0.f, by = 0.f;
                if (m == 0) { float2 bb = *(const float2*)&b1[c]; bx = bb.x; by = bb.y; }
                else if (m == 2) { float2 bb = *(const float2*)&b3[c]; bx = bb.x; by = bb.y; }
                *(__half2*)&sh_h[rl1 * 72 + c] = __floats2half2_rn(a[0] + bx, a[1] + by);
                *(__half2*)&sh_h[rl2 * 72 + c] = __floats2half2_rn(a[2] + bx, a[3] + by);
            }
            __syncthreads();
            __half* dstp = (m == 0) ? g_Ah : ((m == 1) ? g_Bh : g_Ch);
            for (int p = tid; p < 512; p += 256) {
                int row = p >> 3, col8 = (p & 7) * 8;
                int gn = nbase + row;
                if (gn < NN)
                    *(uint4*)&dstp[gn * 64 + col8] = *(const uint4*)&sh_h[row * 72 + col8];
            }
        }
    }
}

// -------- gather: h = relu( sum_e w*A[src] + C - wsum*B ), warp per node -----
// LAST layer also computes node attention natt.
template <bool LAST>
__global__ void k_gather() {
    int gt = blockIdx.x * 256 + threadIdx.x;
    int node = gt >> 5, lane = gt & 31;
    if (node >= NN) return;
    int s = g_rs[node];
    int len = g_cnt[node];
    int e = s + len;
    int loff = lane * 2;
    float ax0 = 0.f, ay0 = 0.f, ax1 = 0.f, ay1 = 0.f;
    float wsum = 0.f, asum = 0.f;
    for (int base = s; base < e; base += 32) {
        int idx = base + lane;
        float4 ce = make_float4(0.f, 0.f, 0.f, 0.f);
        if (idx < e) ce = g_ce[idx];
        int sn = __float_as_int(ce.x);
        float wv = ce.y;
        if (LAST) asum += ce.z;
        int m = min(32, e - base);
        int mr = (m + 7) & ~7;
        for (int j = 0; j < mr; j += 8) {
            int s0 = __shfl_sync(0xffffffffu, sn, j);
            int s1 = __shfl_sync(0xffffffffu, sn, j + 1);
            int s2 = __shfl_sync(0xffffffffu, sn, j + 2);
            int s3 = __shfl_sync(0xffffffffu, sn, j + 3);
            int s4 = __shfl_sync(0xffffffffu, sn, j + 4);
            int s5 = __shfl_sync(0xffffffffu, sn, j + 5);
            int s6 = __shfl_sync(0xffffffffu, sn, j + 6);
            int s7 = __shfl_sync(0xffffffffu, sn, j + 7);
            float w0 = __shfl_sync(0xffffffffu, wv, j);
            float w1 = __shfl_sync(0xffffffffu, wv, j + 1);
            float w2 = __shfl_sync(0xffffffffu, wv, j + 2);
            float w3 = __shfl_sync(0xffffffffu, wv, j + 3);
            float w4 = __shfl_sync(0xffffffffu, wv, j + 4);
            float w5 = __shfl_sync(0xffffffffu, wv, j + 5);
            float w6 = __shfl_sync(0xffffffffu, wv, j + 6);
            float w7 = __shfl_sync(0xffffffffu, wv, j + 7);
            __half2 h0 = __ldg((const __half2*)&g_Ah[s0 * 64 + loff]);
            __half2 h1 = __ldg((const __half2*)&g_Ah[s1 * 64 + loff]);
            __half2 h2 = __ldg((const __half2*)&g_Ah[s2 * 64 + loff]);
            __half2 h3 = __ldg((const __half2*)&g_Ah[s3 * 64 + loff]);
            __half2 h4 = __ldg((const __half2*)&g_Ah[s4 * 64 + loff]);
            __half2 h5 = __ldg((const __half2*)&g_Ah[s5 * 64 + loff]);
            __half2 h6 = __ldg((const __half2*)&g_Ah[s6 * 64 + loff]);
            __half2 h7 = __ldg((const __half2*)&g_Ah[s7 * 64 + loff]);
            float2 v0 = __half22float2(h0);
            float2 v1 = __half22float2(h1);
            float2 v2 = __half22float2(h2);
            float2 v3 = __half22float2(h3);
            float2 v4 = __half22float2(h4);
            float2 v5 = __half22float2(h5);
            float2 v6 = __half22float2(h6);
            float2 v7 = __half22float2(h7);
            wsum += ((w0 + w1) + (w2 + w3)) + ((w4 + w5) + (w6 + w7));
            ax0 = fmaf(w0, v0.x, ax0); ay0 = fmaf(w0, v0.y, ay0);
            ax1 = fmaf(w1, v1.x, ax1); ay1 = fmaf(w1, v1.y, ay1);
            ax0 = fmaf(w2, v2.x, ax0); ay0 = fmaf(w2, v2.y, ay0);
            ax1 = fmaf(w3, v3.x, ax1); ay1 = fmaf(w3, v3.y, ay1);
            ax0 = fmaf(w4, v4.x, ax0); ay0 = fmaf(w4, v4.y, ay0);
            ax1 = fmaf(w5, v5.x, ax1); ay1 = fmaf(w5, v5.y, ay1);
            ax0 = fmaf(w6, v6.x, ax0); ay0 = fmaf(w6, v6.y, ay0);
            ax1 = fmaf(w7, v7.x, ax1); ay1 = fmaf(w7, v7.y, ay1);
        }
    }
    float2 bv = __half22float2(*(const __half2*)&g_Bh[node * 64 + loff]);
    float2 cv = __half22float2(*(const __half2*)&g_Ch[node * 64 + loff]);
    float hx = fmaxf(ax0 + ax1 + cv.x - wsum * bv.x, 0.f);
    float hy = fmaxf(ay0 + ay1 + cv.y - wsum * bv.y, 0.f);
    *(__half2*)&g_hh[node * 64 + loff] = __floats2half2_rn(hx, hy);
    if (LAST) {
#pragma unroll
        for (int o = 16; o > 0; o >>= 1)
            asum += __shfl_down_sync(0xffffffffu, asum, o);
        if (lane == 0) {
            float att_tot = asum + g_atts[node];
            float deg = (float)(len + g_degs[node]);
            g_natt[node] = att_tot / ((deg == 0.f) ? 1.f : deg);
        }
    }
}

// ------- fused pooling + MLP + scratch re-zero for next replay ---------------
__global__ void k_poolmlp(const int* __restrict__ batch,
                          const float* __restrict__ f1w, const float* __restrict__ f1b,
                          const float* __restrict__ f2w, const float* __restrict__ f2b,
                          float* __restrict__ out) {
    int g = blockIdx.x, tid = threadIdx.x;  // 128
    __shared__ int se[2];
    __shared__ float sacc[128], satt[128];
    __shared__ float sx[64], shh[128];

    int tg = g * 128 + tid;  // 0..65535
    for (int i = tg; i < NN; i += NGR * 128) {
        g_cnt[i] = 0; g_atts[i] = 0.f; g_degs[i] = 0;
    }
    if (tg < 128) g_bsum[tg] = 0;
    if (tg == 0) g_tick = 0;

    if (tid < 2) {
        int key = g + tid;
        int lo = 0, hi = NN;
        while (lo < hi) {
            int mid = (lo + hi) >> 1;
            if (batch[mid] < key) lo = mid + 1; else hi = mid;
        }
        se[tid] = lo;
    }
    __syncthreads();
    int s = se[0], e = se[1];
    int c = tid & 63, part = tid >> 6;
    float acc = 0.f, att = 0.f;
    for (int i = s + part; i < e; i += 2) {
        float na = g_natt[i];
        acc = fmaf(__half2float(g_hh[i * 64 + c]), na, acc);
        att += na;
    }
    sacc[tid] = acc; satt[tid] = att;
    __syncthreads();
    if (tid < 64) {
        float a = sacc[tid] + sacc[tid + 64];
        float at = satt[0] + satt[64];
        float cnt = (float)(e - s);
        float gat = (at == 0.f) ? 1.f : at;
        float scale = cnt / (gat * fmaxf(cnt, 1.f));
        sx[tid] = a * scale;
    }
    __syncthreads();
    float a = f1b[tid];
#pragma unroll 8
    for (int k = 0; k < 64; k++) a = fmaf(sx[k], f1w[k * 128 + tid], a);
    shh[tid] = fmaxf(a, 0.f);
    __syncthreads();
    if (tid < 3) {
        float o = f2b[tid];
        for (int j = 0; j < 128; j++) o = fmaf(shh[j], f2w[j * 3 + tid], o);
        out[g * 3 + tid] = o;
    }
}

// ---------------- launch ----------------
extern "C" void kernel_launch(void* const* d_in, const int* in_sizes, int n_in,
                              void* d_out, int out_size) {
    const float* x     = (const float*)d_in[0];
    const int*   ei    = (const int*)d_in[1];
    const int*   batch = (const int*)d_in[2];
    const float* eattr = (const float*)d_in[3];
    const float* eatt  = (const float*)d_in[4];
    const float* embw  = (const float*)d_in[5];
    const float* embb  = (const float*)d_in[6];
    const float* l1w   = (const float*)d_in[7];
    const float* l1b   = (const float*)d_in[8];
    const float* l2w   = (const float*)d_in[9];
    const float* l3w   = (const float*)d_in[10];
    const float* l3b   = (const float*)d_in[11];
    const float* f1w   = (const float*)d_in[12];
    const float* f1b   = (const float*)d_in[13];
    const float* f2w   = (const float*)d_in[14];
    const float* f2b   = (const float*)d_in[15];
    float* out = (float*)d_out;

    const int smem_gemm = (64 * 72 + 3 * 64 * 72) * 2;  // 36864 B
    const int* src = ei;
    const int* dst = ei + NE;

    int sms = 148;
    cudaDeviceGetAttribute(&sms, cudaDevAttrMultiProcessorCount, 0);
    int gemm_blocks = sms * 3;

    k_initedge<<<(NN * 32 + 255) / 256, 256>>>(x, embw, embb, dst, l1w, l2w, l3w);
    k_scan<<<(NN + 1023) / 1024, 256>>>();
    k_fill<<<(NE / 4 + 255) / 256, 256>>>(src, dst, eattr, eatt);

    for (int l = 0; l < 3; l++) {
        k_gemm<<<gemm_blocks, 256, smem_gemm>>>(l, l1b + l * 64, l3b + l * 64);
        if (l < 2)
            k_gather<false><<<(NN * 32 + 255) / 256, 256>>>();
        else
            k_gather<true><<<(NN * 32 + 255) / 256, 256>>>();
    }

    k_poolmlp<<<NGR, 128>>>(batch, f1w, f1b, f2w, f2b, out);
}